// round 14
// baseline (speedup 1.0000x reference)
#include <cuda_runtime.h>
#include <math.h>

#define BATCH   16
#define NPB     36864      // boxes per batch = 64*64*9
#define THREADS 1024
#define PER_TH  36         // NPB / THREADS
#define TOPN    300
#define NGT     64
#define TPOS    64
#define NBUCK   4096
#define SLABSZ  7936u
#define NSLAB   5          // ceil(36864/7936)
#define PPOW    8192       // slab capacity
#define CHK     512        // NMS chunk size
#define QCAP    24         // deferred full-test queue capacity

// L2-resident scratch (no cudaMalloc allowed)
__device__ float4   g_boxes[BATCH * NPB];
__device__ unsigned g_k30[BATCH * NPB];

// dynamic smem layout (u32 units):
//  [0, 16384)        s_key u64[8192]   (aliased by s_hist u32[4096] in phase A)
//  [16384, 20481)    s_cum u32[4097]  (+pad to 20484)
//  [20484, 24580)    s_bpos u32[4096]
//  [24580, 26628)    s_kbox float4[512]
//  [26628, 34820)    s_mask u32[512*16]
#define OFF_CUM   16384
#define OFF_BPOS  20484
#define OFF_KBOX  24580
#define OFF_MASK  26628
#define DYN_U32   34820
#define DYN_BYTES (DYN_U32 * 4)

// bucket from descending key30 (monotone coarsening): uniform in score VALUE.
__device__ __forceinline__ unsigned bucket_of(unsigned key30) {
    float s = __uint_as_float(0x3F7FFFFFu - key30);
    unsigned q = (unsigned)__fmul_rn(s, 4096.f);
    if (q > 4095u) q = 4095u;
    return 4095u - q;
}

// Exact-threshold suppression test: guard band + exact division fallback.
__device__ __forceinline__ bool suppress_test(float4 sb, float sa, float4 bx, float ab) {
    float yy1 = fmaxf(sb.x, bx.x);
    float xx1 = fmaxf(sb.y, bx.y);
    float yy2 = fminf(sb.z, bx.z);
    float xx2 = fminf(sb.w, bx.w);
    float ih  = fmaxf(__fsub_rn(yy2, yy1), 0.f);
    float iw  = fmaxf(__fsub_rn(xx2, xx1), 0.f);
    float inter = __fmul_rn(ih, iw);
    float denom = __fadd_rn(__fsub_rn(__fadd_rn(sa, ab), inter), 1e-7f);
    float e = __fmaf_rn(-0.5f, denom, inter);
    float margin = __fmul_rn(denom, 1e-4f);
    if (e < -margin) return false;
    if (e >  margin) return true;
    return __fdiv_rn(inter, denom) >= 0.5f;       // exact reference semantics
}

// Quantized screen word: bytes (qcy, qh, qcx, qw).
// qcy/qcx: center * 64 + 96 (clamped; clamping only widens the pass set).
// qh/qw: half-extent in the SAME scale: h * 32, floor + 2 (>= true value + 1).
// Screen condition uses |dc| <= qh_s + qh_c + 3: fail => axis overlap impossible.
__device__ __forceinline__ unsigned pack_box(float4 b) {
    float cy = __fmul_rn(0.5f, __fadd_rn(b.x, b.z));
    float cx = __fmul_rn(0.5f, __fadd_rn(b.y, b.w));
    float h  = __fsub_rn(b.z, b.x);
    float w  = __fsub_rn(b.w, b.y);
    int qcy = (int)(__fmaf_rn(cy, 64.f, 96.f));
    int qcx = (int)(__fmaf_rn(cx, 64.f, 96.f));
    qcy = qcy < 0 ? 0 : (qcy > 255 ? 255 : qcy);
    qcx = qcx < 0 ? 0 : (qcx > 255 ? 255 : qcx);
    int qh = (int)(__fmul_rn(h, 32.f)) + 2; if (qh > 255) qh = 255;
    int qw = (int)(__fmul_rn(w, 32.f)) + 2; if (qw > 255) qw = 255;
    return (unsigned)qcy | ((unsigned)qh << 8) | ((unsigned)qcx << 16) | ((unsigned)qw << 24);
}

__device__ __forceinline__ bool screen_pass(unsigned s, unsigned c) {
    unsigned d   = __vabsdiffu4(s, c);            // [dcy, dh, dcx, dw]
    unsigned sum = __vaddus4(s, c);               // [.., hs+hc, .., ws+wc]
    unsigned thr = __vaddus4(sum >> 8, 0x00030003u); // b0 = hsum+3, b2 = wsum+3
    unsigned le  = __vcmpleu4(d, thr);
    return (le & 0x00FF00FFu) == 0x00FF00FFu;
}

__global__ void __launch_bounds__(THREADS, 1)
roi_kernel(const float* __restrict__ deltas,
           const float* __restrict__ labels,
           const float* __restrict__ anchors,
           const float* __restrict__ gt,
           float* __restrict__ out)
{
    extern __shared__ unsigned s_dyn[];
    unsigned long long* s_key = (unsigned long long*)s_dyn;
    unsigned* s_hist = s_dyn;                        // alias (phase A only)
    unsigned* s_cum  = s_dyn + OFF_CUM;              // 4097 entries
    unsigned* s_bpos = s_dyn + OFF_BPOS;             // per-slab bucket counters
    float4*   s_kbox = (float4*)(s_dyn + OFF_KBOX);  // 512 compacted boxes
    unsigned* s_mask = s_dyn + OFF_MASK;             // 512 rows x 16 words

    __shared__ float4 s_sel[TOPN];
    __shared__ float  s_sela[TOPN];
    __shared__ unsigned s_selpk[TOPN];
    __shared__ float4 s_nms[TOPN];
    __shared__ float  s_merged[TOPN];
    __shared__ int    s_gtbest[TOPN];
    __shared__ float4 s_gt4[NGT];
    __shared__ unsigned s_warp[32];
    __shared__ unsigned s_kalA[16], s_kalB[16];
    __shared__ int    s_ncur, s_m, s_M;

    const int b = blockIdx.x;
    const int t = threadIdx.x;
    const int lane = t & 31, wid = t >> 5;
    const int p    = t & (CHK - 1);   // candidate slot within chunk
    const int grp  = t >> 9;          // 0 or 1

    const float4* anc4 = (const float4*)(anchors) + (size_t)b * NPB;
    const float4* dlt4 = (const float4*)(deltas)  + (size_t)b * NPB;
    const float*  lab  = labels + (size_t)b * NPB;
    float4*   boxes = g_boxes + (size_t)b * NPB;
    unsigned* k30g  = g_k30  + (size_t)b * NPB;

    // ================= Phase A: decode + key30 + bucket histogram ==========
    #pragma unroll
    for (int c = 0; c < 4; ++c) s_hist[c * 1024 + t] = 0;
    if (t == 0) s_ncur = 0;
    __syncthreads();

    #pragma unroll 4
    for (int k = 0; k < PER_TH; ++k) {
        int i = t + k * THREADS;
        float4 a = anc4[i];
        float4 d = dlt4[i];
        float ah  = __fsub_rn(a.z, a.x);
        float aw  = __fsub_rn(a.w, a.y);
        float acy = __fadd_rn(a.x, __fmul_rn(0.5f, ah));
        float acx = __fadd_rn(a.y, __fmul_rn(0.5f, aw));
        float h   = __fmul_rn(expf(d.z), ah);
        float w   = __fmul_rn(expf(d.w), aw);
        float cy  = __fadd_rn(__fmul_rn(d.x, ah), acy);
        float cx  = __fadd_rn(__fmul_rn(d.y, aw), acx);
        float y1  = __fsub_rn(cy, __fmul_rn(0.5f, h));
        float x1  = __fsub_rn(cx, __fmul_rn(0.5f, w));
        boxes[i]  = make_float4(y1, x1, __fadd_rn(y1, h), __fadd_rn(x1, w));
        unsigned key30 = 0x3F7FFFFFu - __float_as_uint(lab[i]);
        k30g[i] = key30;
        atomicAdd(&s_hist[bucket_of(key30)], 1u);
    }
    __syncthreads();

    // ================= Phase B: exclusive scan of 4096 bucket counts =======
    {
        unsigned v[4], sum = 0;
        #pragma unroll
        for (int j = 0; j < 4; ++j) { v[j] = s_hist[t * 4 + j]; }
        unsigned e[4];
        #pragma unroll
        for (int j = 0; j < 4; ++j) { e[j] = sum; sum += v[j]; }
        unsigned x = sum;
        #pragma unroll
        for (int o = 1; o < 32; o <<= 1) {
            unsigned y = __shfl_up_sync(0xffffffffu, x, o);
            if (lane >= o) x += y;
        }
        if (lane == 31) s_warp[wid] = x;
        __syncthreads();
        if (t < 32) {
            unsigned wsum = s_warp[t], xx = wsum;
            #pragma unroll
            for (int o = 1; o < 32; o <<= 1) {
                unsigned y = __shfl_up_sync(0xffffffffu, xx, o);
                if (t >= o) xx += y;
            }
            s_warp[t] = xx - wsum;
        }
        __syncthreads();
        unsigned prefix = s_warp[wid] + (x - sum);
        #pragma unroll
        for (int j = 0; j < 4; ++j) s_cum[t * 4 + j] = prefix + e[j];
        if (t == THREADS - 1) s_cum[NBUCK] = prefix + sum;
        __syncthreads();
    }

    // ========== Phase C: slabs (placed gather -> bucket sort -> NMS) =======
    int base = 0;                          // running slab base (uniform)
    for (int slab = 0; slab < NSLAB; ++slab) {
        if (s_ncur >= TOPN) break;         // uniform (post-sync)
        if (t == 0) s_m = 0;
        #pragma unroll
        for (int c = 0; c < 4; ++c) s_bpos[c * 1024 + t] = 0;
        __syncthreads();

        // placed gather: element goes straight to its bucket's slab range
        #pragma unroll 4
        for (int k = 0; k < PER_TH; ++k) {
            int i = t + k * THREADS;
            unsigned key30 = k30g[i];
            unsigned bk = bucket_of(key30);
            if (s_cum[bk] / SLABSZ == (unsigned)slab) {
                int pos = (int)(s_cum[bk] - (unsigned)base) + (int)atomicAdd(&s_bpos[bk], 1u);
                s_key[pos] = ((unsigned long long)key30 << 16) | (unsigned)i;
                atomicAdd(&s_m, 1);
            }
        }
        __syncthreads();
        int m = s_m;
        for (int i = t; i < PPOW; i += THREADS)
            if (i >= m) s_key[i] = ~0ull;
        __syncthreads();

        // per-bucket insertion sort IN SMEM (keys unique => deterministic)
        #pragma unroll
        for (int c = 0; c < 4; ++c) {
            int bk = t + c * THREADS;
            if (s_cum[bk] / SLABSZ == (unsigned)slab) {
                int lo = (int)(s_cum[bk] - (unsigned)base);
                int n  = (int)s_bpos[bk];
                for (int i2 = lo + 1; i2 < lo + n; ++i2) {
                    unsigned long long v = s_key[i2];
                    int j2 = i2 - 1;
                    while (j2 >= lo && s_key[j2] > v) { s_key[j2 + 1] = s_key[j2]; --j2; }
                    s_key[j2 + 1] = v;
                }
            }
        }
        __syncthreads();

        // NMS over sorted slab in chunks of CHK
        for (int pos = 0; pos < m; pos += CHK) {
            if (s_ncur >= TOPN) break;        // uniform (post-sync)
            int nc = s_ncur;

            // ---- load candidate (both groups hold the same box) ----
            int ci = pos + p;
            bool valid = ci < m;
            float4 bx = make_float4(0.f, 0.f, 0.f, 0.f);
            float  ab = 0.f;
            unsigned cpk = 0;
            if (valid) {
                unsigned gidx = (unsigned)(s_key[ci] & 0xFFFFu);
                bx = boxes[gidx];
                ab = __fmul_rn(__fsub_rn(bx.z, bx.x), __fsub_rn(bx.w, bx.y));
                cpk = pack_box(bx);
            }

            // ---- split prekill: SIMD screen sweep + deferred exact tests ---
            int ncA = (nc + 1) >> 1;
            int j0 = grp ? ncA : 0;
            int j1 = grp ? nc  : ncA;
            bool kill = !valid;
            if (valid) {
                unsigned short q[QCAP];
                int qn = 0;
                for (int j = j0; j < j1; ++j) {
                    if (screen_pass(s_selpk[j], cpk)) {
                        if (qn < QCAP) q[qn++] = (unsigned short)j;
                        else if (!kill)
                            kill = suppress_test(s_sel[j], s_sela[j], bx, ab);
                    }
                }
                for (int k2 = 0; k2 < qn && !kill; ++k2) {
                    int j = (int)q[k2];
                    kill = suppress_test(s_sel[j], s_sela[j], bx, ab);
                }
            }
            unsigned kb = __ballot_sync(0xffffffffu, kill);
            if (lane == 0) { if (grp == 0) s_kalA[wid] = kb; else s_kalB[wid - 16] = kb; }
            __syncthreads();

            // ---- merge kill info, compact alive (order-preserving) ----
            bool alive = false;
            if (grp == 0) {
                unsigned kw = s_kalA[p >> 5] | s_kalB[p >> 5];
                alive = valid && !((kw >> (p & 31)) & 1u);
            }
            unsigned bal = __ballot_sync(0xffffffffu, alive);
            if (lane == 0) s_warp[wid] = __popc(bal);
            __syncthreads();
            if (t < 32) {
                unsigned wsum = s_warp[t], xx = wsum;
                #pragma unroll
                for (int o = 1; o < 32; o <<= 1) {
                    unsigned y = __shfl_up_sync(0xffffffffu, xx, o);
                    if (t >= o) xx += y;
                }
                s_warp[t] = xx - wsum;
                if (t == 31) s_M = (int)xx;
            }
            __syncthreads();
            if (alive) {
                int cpos = (int)s_warp[wid] + __popc(bal & ((1u << lane) - 1u));
                s_kbox[cpos] = bx;
            }
            // zero suppression mask (512x16 words)
            #pragma unroll
            for (int w = 0; w < 8; ++w) s_mask[w * 1024 + t] = 0;
            __syncthreads();
            int M = s_M;
            if (M == 0) continue;             // uniform

            // ---- pair enumeration among compacted survivors ----
            if (M >= 2 && p < M) {
                int half = M >> 1;
                float4 P = s_kbox[p];
                float pa = __fmul_rn(__fsub_rn(P.z, P.x), __fsub_rn(P.w, P.y));
                for (int d = 1 + grp; d <= half; d += 2) {
                    int o = p + d; if (o >= M) o -= M;
                    int a = p < o ? p : o;    // earlier = suppressor
                    int c = p < o ? o : p;
                    float4 C = s_kbox[o];
                    float ca = __fmul_rn(__fsub_rn(C.z, C.x), __fsub_rn(C.w, C.y));
                    if (suppress_test(P, pa, C, ca))
                        atomicOr(&s_mask[a * 16 + (c >> 5)], 1u << (c & 31));
                }
            }
            __syncthreads();

            // ---- warp0 greedy resolution over the bitmask (no block BARs) --
            if (t < 32) {
                unsigned dead = 0;
                unsigned aliveW = 0;
                if (t < 16) {
                    int bb = t * 32;
                    int rem = M - bb;
                    aliveW = (rem >= 32) ? 0xffffffffu
                           : (rem > 0 ? ((1u << rem) - 1u) : 0u);
                }
                int n = nc;
                for (int w = 0; w < 16 && n < TOPN; ++w) {
                    unsigned cur = __shfl_sync(0xffffffffu, aliveW & ~dead, w);
                    while (cur && n < TOPN) {
                        int bitp = __ffs(cur) - 1;
                        int i = w * 32 + bitp;
                        cur &= cur - 1;
                        if (t == 0) {
                            float4 sb = s_kbox[i];
                            s_sel[n] = sb;
                            s_sela[n] = __fmul_rn(__fsub_rn(sb.z, sb.x),
                                                  __fsub_rn(sb.w, sb.y));
                            s_selpk[n] = pack_box(sb);
                        }
                        n++;
                        unsigned row = (t < 16) ? s_mask[i * 16 + t] : 0u;
                        dead |= row;
                        unsigned rw = __shfl_sync(0xffffffffu, row, w);
                        cur &= ~rw;
                    }
                }
                if (t == 0) s_ncur = n;
            }
            __syncthreads();
        }
        __syncthreads();
        base += m;                           // uniform (m read post-sync)
    }
    __syncthreads();
    const int nsel = s_ncur;

    // ================= Phase D: clip, select_rois, rank, emit ==============
    for (int j = t; j < TOPN; j += THREADS) {
        float4 bxo = make_float4(0.f, 0.f, 0.f, 0.f);
        if (j < nsel) {
            float4 vv = s_sel[j];
            bxo.x = fminf(fmaxf(vv.x, 0.f), 1.f);
            bxo.y = fminf(fmaxf(vv.y, 0.f), 1.f);
            bxo.z = fminf(fmaxf(vv.z, 0.f), 1.f);
            bxo.w = fminf(fmaxf(vv.w, 0.f), 1.f);
        }
        s_nms[j] = bxo;
    }
    for (int j = t; j < NGT; j += THREADS) {
        s_gt4[j] = ((const float4*)gt)[(size_t)b * NGT + j];
    }
    __syncthreads();

    if (t < TOPN) {
        float4 a = s_nms[t];
        float aa = __fmul_rn(__fsub_rn(a.z, a.x), __fsub_rn(a.w, a.y));
        float mg = -1.f; int bi = 0;
        #pragma unroll 4
        for (int g = 0; g < NGT; ++g) {
            float4 gb = s_gt4[g];
            float yy1 = fmaxf(a.x, gb.x);
            float xx1 = fmaxf(a.y, gb.y);
            float yy2 = fminf(a.z, gb.z);
            float xx2 = fminf(a.w, gb.w);
            float inter = __fmul_rn(fmaxf(__fsub_rn(yy2, yy1), 0.f),
                                    fmaxf(__fsub_rn(xx2, xx1), 0.f));
            float gba = __fmul_rn(__fsub_rn(gb.z, gb.x), __fsub_rn(gb.w, gb.y));
            float denom = __fadd_rn(__fsub_rn(__fadd_rn(aa, gba), inter), 1e-7f);
            float iou = __fdiv_rn(inter, denom);
            if (iou > mg) { mg = iou; bi = g; }
        }
        s_merged[t] = mg; s_gtbest[t] = bi;
    }
    __syncthreads();

    if (t < TOPN) {
        float mg = s_merged[t];
        int r = 0;
        for (int j = 0; j < TOPN; ++j) {
            float mj = s_merged[j];
            if (mj > mg || (mj == mg && j < t)) ++r;
        }
        if (r < TPOS) {
            float4 a = s_nms[t];
            float* roi = out + ((size_t)b * 128 + r) * 4;
            roi[0] = a.x; roi[1] = a.y; roi[2] = a.z; roi[3] = a.w;
            out[(size_t)BATCH * 128 * 4 + (size_t)b * TPOS + r] = (float)s_gtbest[t];
        }
    }
    for (int j = t; j < 64 * 4; j += THREADS) {
        out[((size_t)b * 128 + TPOS) * 4 + j] = 0.f;
    }
}

extern "C" void kernel_launch(void* const* d_in, const int* in_sizes, int n_in,
                              void* d_out, int out_size) {
    const float* deltas  = (const float*)d_in[0];
    const float* labels  = (const float*)d_in[1];
    const float* anchors = (const float*)d_in[2];
    const float* gt      = (const float*)d_in[3];
    float* out = (float*)d_out;
    cudaFuncSetAttribute(roi_kernel, cudaFuncAttributeMaxDynamicSharedMemorySize,
                         DYN_BYTES);
    roi_kernel<<<BATCH, THREADS, DYN_BYTES>>>(deltas, labels, anchors, gt, out);
}

// round 15
// speedup vs baseline: 1.1712x; 1.1712x over previous
#include <cuda_runtime.h>
#include <math.h>

#define BATCH   16
#define NPB     36864      // boxes per batch = 64*64*9
#define THREADS 1024
#define PER_TH  36         // NPB / THREADS
#define TOPN    300
#define NGT     64
#define TPOS    64
#define NBUCK   4096
#define SLABSZ  7936u
#define NSLAB   5          // ceil(36864/7936)
#define PPOW    8192       // slab capacity
#define CHK     512        // NMS chunk size

// L2-resident scratch (no cudaMalloc allowed)
__device__ float4   g_boxes[BATCH * NPB];
__device__ unsigned g_k30[BATCH * NPB];

// dynamic smem layout (u32 units):
//  [0, 16384)        s_key u64[8192]   (aliased by s_hist u32[4096] in phase A)
//  [16384, 20481)    s_cum u32[4097]  (+pad to 20484)
//  [20484, 24580)    s_bpos u32[4096]
//  [24580, 26628)    s_kbox float4[512]
//  [26628, 34820)    s_mask u32[512*16]
//  [34820, 36868)    s_cbox float4[512]
//  [36868, 37380)    s_cab  f32[512]
//  [37380, 37508)    s_perm u16[512]
//  [37508, 37764)    s_kill u8[1024]
//  [37764, 37892)    s_ckey u8[512]
#define OFF_CUM   16384
#define OFF_BPOS  20484
#define OFF_KBOX  24580
#define OFF_MASK  26628
#define OFF_CBOX  34820
#define OFF_CAB   36868
#define OFF_PERM  37380
#define OFF_KILL  37508
#define OFF_CKEY  37764
#define DYN_U32   37892
#define DYN_BYTES (DYN_U32 * 4)

// bucket from descending key30 (monotone coarsening): uniform in score VALUE.
__device__ __forceinline__ unsigned bucket_of(unsigned key30) {
    float s = __uint_as_float(0x3F7FFFFFu - key30);
    unsigned q = (unsigned)__fmul_rn(s, 4096.f);
    if (q > 4095u) q = 4095u;
    return 4095u - q;
}

// Exact-threshold suppression test: guard band + exact division fallback.
__device__ __forceinline__ bool suppress_test(float4 sb, float sa, float4 bx, float ab) {
    float yy1 = fmaxf(sb.x, bx.x);
    float xx1 = fmaxf(sb.y, bx.y);
    float yy2 = fminf(sb.z, bx.z);
    float xx2 = fminf(sb.w, bx.w);
    float ih  = fmaxf(__fsub_rn(yy2, yy1), 0.f);
    float iw  = fmaxf(__fsub_rn(xx2, xx1), 0.f);
    float inter = __fmul_rn(ih, iw);
    float denom = __fadd_rn(__fsub_rn(__fadd_rn(sa, ab), inter), 1e-7f);
    float e = __fmaf_rn(-0.5f, denom, inter);
    float margin = __fmul_rn(denom, 1e-4f);
    if (e < -margin) return false;
    if (e >  margin) return true;
    return __fdiv_rn(inter, denom) >= 0.5f;       // exact reference semantics
}

__global__ void __launch_bounds__(THREADS, 1)
roi_kernel(const float* __restrict__ deltas,
           const float* __restrict__ labels,
           const float* __restrict__ anchors,
           const float* __restrict__ gt,
           float* __restrict__ out)
{
    extern __shared__ unsigned s_dyn[];
    unsigned long long* s_key = (unsigned long long*)s_dyn;
    unsigned* s_hist = s_dyn;                        // alias (phase A only)
    unsigned* s_cum  = s_dyn + OFF_CUM;              // 4097 entries
    unsigned* s_bpos = s_dyn + OFF_BPOS;             // per-slab bucket counters
    float4*   s_kbox = (float4*)(s_dyn + OFF_KBOX);  // 512 compacted boxes
    unsigned* s_mask = s_dyn + OFF_MASK;             // 512 rows x 16 words
    float4*   s_cbox = (float4*)(s_dyn + OFF_CBOX);  // 512 chunk boxes
    float*    s_cab  = (float*)(s_dyn + OFF_CAB);    // 512 chunk areas
    unsigned short* s_perm = (unsigned short*)(s_dyn + OFF_PERM);
    unsigned char*  s_kill = (unsigned char*)(s_dyn + OFF_KILL);
    unsigned char*  s_ckey = (unsigned char*)(s_dyn + OFF_CKEY);

    __shared__ float4 s_sel[TOPN];
    __shared__ float  s_sela[TOPN];
    __shared__ float4 s_nms[TOPN];
    __shared__ float  s_merged[TOPN];
    __shared__ int    s_gtbest[TOPN];
    __shared__ float4 s_gt4[NGT];
    __shared__ unsigned s_warp[32];
    __shared__ int    s_bh[64], s_bstart[64];
    __shared__ int    s_ncur, s_m, s_M;

    const int b = blockIdx.x;
    const int t = threadIdx.x;
    const int lane = t & 31, wid = t >> 5;
    const int p    = t & (CHK - 1);   // candidate slot within chunk
    const int grp  = t >> 9;          // 0 or 1

    const float4* anc4 = (const float4*)(anchors) + (size_t)b * NPB;
    const float4* dlt4 = (const float4*)(deltas)  + (size_t)b * NPB;
    const float*  lab  = labels + (size_t)b * NPB;
    float4*   boxes = g_boxes + (size_t)b * NPB;
    unsigned* k30g  = g_k30  + (size_t)b * NPB;

    // ================= Phase A: decode + key30 + bucket histogram ==========
    #pragma unroll
    for (int c = 0; c < 4; ++c) s_hist[c * 1024 + t] = 0;
    if (t == 0) s_ncur = 0;
    __syncthreads();

    #pragma unroll 4
    for (int k = 0; k < PER_TH; ++k) {
        int i = t + k * THREADS;
        float4 a = anc4[i];
        float4 d = dlt4[i];
        float ah  = __fsub_rn(a.z, a.x);
        float aw  = __fsub_rn(a.w, a.y);
        float acy = __fadd_rn(a.x, __fmul_rn(0.5f, ah));
        float acx = __fadd_rn(a.y, __fmul_rn(0.5f, aw));
        float h   = __fmul_rn(expf(d.z), ah);
        float w   = __fmul_rn(expf(d.w), aw);
        float cy  = __fadd_rn(__fmul_rn(d.x, ah), acy);
        float cx  = __fadd_rn(__fmul_rn(d.y, aw), acx);
        float y1  = __fsub_rn(cy, __fmul_rn(0.5f, h));
        float x1  = __fsub_rn(cx, __fmul_rn(0.5f, w));
        boxes[i]  = make_float4(y1, x1, __fadd_rn(y1, h), __fadd_rn(x1, w));
        unsigned key30 = 0x3F7FFFFFu - __float_as_uint(lab[i]);
        k30g[i] = key30;
        atomicAdd(&s_hist[bucket_of(key30)], 1u);
    }
    __syncthreads();

    // ================= Phase B: exclusive scan of 4096 bucket counts =======
    {
        unsigned v[4], sum = 0;
        #pragma unroll
        for (int j = 0; j < 4; ++j) { v[j] = s_hist[t * 4 + j]; }
        unsigned e[4];
        #pragma unroll
        for (int j = 0; j < 4; ++j) { e[j] = sum; sum += v[j]; }
        unsigned x = sum;
        #pragma unroll
        for (int o = 1; o < 32; o <<= 1) {
            unsigned y = __shfl_up_sync(0xffffffffu, x, o);
            if (lane >= o) x += y;
        }
        if (lane == 31) s_warp[wid] = x;
        __syncthreads();
        if (t < 32) {
            unsigned wsum = s_warp[t], xx = wsum;
            #pragma unroll
            for (int o = 1; o < 32; o <<= 1) {
                unsigned y = __shfl_up_sync(0xffffffffu, xx, o);
                if (t >= o) xx += y;
            }
            s_warp[t] = xx - wsum;
        }
        __syncthreads();
        unsigned prefix = s_warp[wid] + (x - sum);
        #pragma unroll
        for (int j = 0; j < 4; ++j) s_cum[t * 4 + j] = prefix + e[j];
        if (t == THREADS - 1) s_cum[NBUCK] = prefix + sum;
        __syncthreads();
    }

    // ========== Phase C: slabs (placed gather -> bucket sort -> NMS) =======
    int base = 0;                          // running slab base (uniform)
    for (int slab = 0; slab < NSLAB; ++slab) {
        if (s_ncur >= TOPN) break;         // uniform (post-sync)
        if (t == 0) s_m = 0;
        #pragma unroll
        for (int c = 0; c < 4; ++c) s_bpos[c * 1024 + t] = 0;
        __syncthreads();

        // placed gather: element goes straight to its bucket's slab range
        #pragma unroll 4
        for (int k = 0; k < PER_TH; ++k) {
            int i = t + k * THREADS;
            unsigned key30 = k30g[i];
            unsigned bk = bucket_of(key30);
            if (s_cum[bk] / SLABSZ == (unsigned)slab) {
                int pos = (int)(s_cum[bk] - (unsigned)base) + (int)atomicAdd(&s_bpos[bk], 1u);
                s_key[pos] = ((unsigned long long)key30 << 16) | (unsigned)i;
                atomicAdd(&s_m, 1);
            }
        }
        __syncthreads();
        int m = s_m;
        for (int i = t; i < PPOW; i += THREADS)
            if (i >= m) s_key[i] = ~0ull;
        __syncthreads();

        // per-bucket insertion sort IN SMEM (keys unique => deterministic)
        #pragma unroll
        for (int c = 0; c < 4; ++c) {
            int bk = t + c * THREADS;
            if (s_cum[bk] / SLABSZ == (unsigned)slab) {
                int lo = (int)(s_cum[bk] - (unsigned)base);
                int n  = (int)s_bpos[bk];
                for (int i2 = lo + 1; i2 < lo + n; ++i2) {
                    unsigned long long v = s_key[i2];
                    int j2 = i2 - 1;
                    while (j2 >= lo && s_key[j2] > v) { s_key[j2 + 1] = s_key[j2]; --j2; }
                    s_key[j2 + 1] = v;
                }
            }
        }
        __syncthreads();

        // NMS over sorted slab in chunks of CHK
        for (int pos = 0; pos < m; pos += CHK) {
            if (s_ncur >= TOPN) break;        // uniform (post-sync)
            int nc = s_ncur;
            int cnt = m - pos; if (cnt > CHK) cnt = CHK;

            // ---- load chunk into smem + spatial/scale key + histogram ----
            if (t < 64) s_bh[t] = 0;
            if (t < CHK) { s_kill[t] = 0; s_kill[CHK + t] = 0; }
            __syncthreads();
            if (t < CHK) {
                if (t < cnt) {
                    unsigned gidx = (unsigned)(s_key[pos + t] & 0xFFFFu);
                    float4 bx = boxes[gidx];
                    float ab = __fmul_rn(__fsub_rn(bx.z, bx.x), __fsub_rn(bx.w, bx.y));
                    s_cbox[t] = bx;
                    s_cab[t] = ab;
                    float cy = __fmul_rn(0.5f, __fadd_rn(bx.x, bx.z));
                    float cx = __fmul_rn(0.5f, __fadd_rn(bx.y, bx.w));
                    int qy = (int)__fmul_rn(cy, 4.f); qy = qy < 0 ? 0 : (qy > 3 ? 3 : qy);
                    int qx = (int)__fmul_rn(cx, 4.f); qx = qx < 0 ? 0 : (qx > 3 ? 3 : qx);
                    int eb = (int)(__float_as_uint(ab) >> 23) - 120;
                    int cls = eb >> 1; cls = cls < 0 ? 0 : (cls > 3 ? 3 : cls);
                    int key = cls * 16 + qy * 4 + qx;
                    s_ckey[t] = (unsigned char)key;
                    atomicAdd(&s_bh[key], 1);
                } else {
                    s_cbox[t] = make_float4(1e30f, 1e30f, -1e30f, -1e30f);
                    s_cab[t] = 0.f;
                    s_ckey[t] = 63;
                    atomicAdd(&s_bh[63], 1);
                }
            }
            __syncthreads();
            // scan 64 bins (warp 0, two halves)
            if (t < 32) {
                int v0 = s_bh[t], v1 = s_bh[32 + t];
                int x0 = v0, x1 = v1;
                #pragma unroll
                for (int o = 1; o < 32; o <<= 1) {
                    int y0 = __shfl_up_sync(0xffffffffu, x0, o);
                    int y1 = __shfl_up_sync(0xffffffffu, x1, o);
                    if (t >= o) { x0 += y0; x1 += y1; }
                }
                int tot0 = __shfl_sync(0xffffffffu, x0, 31);
                s_bstart[t] = x0 - v0;
                s_bstart[32 + t] = tot0 + x1 - v1;
            }
            __syncthreads();
            if (t < CHK) {
                int q = atomicAdd(&s_bstart[s_ckey[t]], 1);
                s_perm[q] = (unsigned short)t;
            }
            __syncthreads();

            // ---- prekill (spatially coherent warps + warp-uniform screen) -
            {
                int cand = (int)s_perm[p];
                float4 bx = s_cbox[cand];
                float  ab = s_cab[cand];
                bool valid = cand < cnt;
                bool kill = !valid;
                // warp bounding box (invalid lanes contribute neutrals)
                float wy1 = bx.x, wx1 = bx.y, wy2 = bx.z, wx2 = bx.w;
                #pragma unroll
                for (int o = 16; o; o >>= 1) {
                    wy1 = fminf(wy1, __shfl_xor_sync(0xffffffffu, wy1, o));
                    wx1 = fminf(wx1, __shfl_xor_sync(0xffffffffu, wx1, o));
                    wy2 = fmaxf(wy2, __shfl_xor_sync(0xffffffffu, wy2, o));
                    wx2 = fmaxf(wx2, __shfl_xor_sync(0xffffffffu, wx2, o));
                }
                int ncA = (nc + 1) >> 1;
                int j0 = grp ? ncA : 0;
                int j1 = grp ? nc  : ncA;
                for (int j = j0; j < j1; ++j) {
                    float4 sb = s_sel[j];
                    // warp-uniform screen: miss => inter==0 for ALL lanes =>
                    // suppress_test is exactly false. Zero approximation.
                    if (sb.z > wy1 && sb.x < wy2 && sb.w > wx1 && sb.y < wx2) {
                        if (!kill) kill = suppress_test(sb, s_sela[j], bx, ab);
                        if (__all_sync(0xffffffffu, kill)) break;
                    }
                }
                s_kill[grp * CHK + cand] = kill ? 1 : 0;
            }
            __syncthreads();

            // ---- merge kill flags, compact alive (original order) ----
            bool alive = false;
            if (grp == 0)
                alive = (p < cnt) && !(s_kill[p] | s_kill[CHK + p]);
            unsigned bal = __ballot_sync(0xffffffffu, alive);
            if (lane == 0) s_warp[wid] = __popc(bal);
            __syncthreads();
            if (t < 32) {
                unsigned wsum = s_warp[t], xx = wsum;
                #pragma unroll
                for (int o = 1; o < 32; o <<= 1) {
                    unsigned y = __shfl_up_sync(0xffffffffu, xx, o);
                    if (t >= o) xx += y;
                }
                s_warp[t] = xx - wsum;
                if (t == 31) s_M = (int)xx;
            }
            __syncthreads();
            if (alive) {
                int cpos = (int)s_warp[wid] + __popc(bal & ((1u << lane) - 1u));
                s_kbox[cpos] = s_cbox[p];
            }
            // zero suppression mask (512x16 words)
            #pragma unroll
            for (int w = 0; w < 8; ++w) s_mask[w * 1024 + t] = 0;
            __syncthreads();
            int M = s_M;
            if (M == 0) continue;             // uniform

            // ---- pair enumeration among compacted survivors ----
            if (M >= 2 && p < M) {
                int half = M >> 1;
                float4 P = s_kbox[p];
                float pa = __fmul_rn(__fsub_rn(P.z, P.x), __fsub_rn(P.w, P.y));
                for (int d = 1 + grp; d <= half; d += 2) {
                    int o = p + d; if (o >= M) o -= M;
                    int a = p < o ? p : o;    // earlier = suppressor
                    int c = p < o ? o : p;
                    float4 C = s_kbox[o];
                    float ca = __fmul_rn(__fsub_rn(C.z, C.x), __fsub_rn(C.w, C.y));
                    if (suppress_test(P, pa, C, ca))
                        atomicOr(&s_mask[a * 16 + (c >> 5)], 1u << (c & 31));
                }
            }
            __syncthreads();

            // ---- warp0 greedy resolution over the bitmask (no block BARs) --
            if (t < 32) {
                unsigned dead = 0;
                unsigned aliveW = 0;
                if (t < 16) {
                    int bb = t * 32;
                    int rem = M - bb;
                    aliveW = (rem >= 32) ? 0xffffffffu
                           : (rem > 0 ? ((1u << rem) - 1u) : 0u);
                }
                int n = nc;
                for (int w = 0; w < 16 && n < TOPN; ++w) {
                    unsigned cur = __shfl_sync(0xffffffffu, aliveW & ~dead, w);
                    while (cur && n < TOPN) {
                        int bitp = __ffs(cur) - 1;
                        int i = w * 32 + bitp;
                        cur &= cur - 1;
                        if (t == 0) {
                            float4 sb = s_kbox[i];
                            s_sel[n] = sb;
                            s_sela[n] = __fmul_rn(__fsub_rn(sb.z, sb.x),
                                                  __fsub_rn(sb.w, sb.y));
                        }
                        n++;
                        unsigned row = (t < 16) ? s_mask[i * 16 + t] : 0u;
                        dead |= row;
                        unsigned rw = __shfl_sync(0xffffffffu, row, w);
                        cur &= ~rw;
                    }
                }
                if (t == 0) s_ncur = n;
            }
            __syncthreads();
        }
        __syncthreads();
        base += m;                           // uniform (m read post-sync)
    }
    __syncthreads();
    const int nsel = s_ncur;

    // ================= Phase D: clip, select_rois, rank, emit ==============
    for (int j = t; j < TOPN; j += THREADS) {
        float4 bxo = make_float4(0.f, 0.f, 0.f, 0.f);
        if (j < nsel) {
            float4 vv = s_sel[j];
            bxo.x = fminf(fmaxf(vv.x, 0.f), 1.f);
            bxo.y = fminf(fmaxf(vv.y, 0.f), 1.f);
            bxo.z = fminf(fmaxf(vv.z, 0.f), 1.f);
            bxo.w = fminf(fmaxf(vv.w, 0.f), 1.f);
        }
        s_nms[j] = bxo;
    }
    for (int j = t; j < NGT; j += THREADS) {
        s_gt4[j] = ((const float4*)gt)[(size_t)b * NGT + j];
    }
    __syncthreads();

    if (t < TOPN) {
        float4 a = s_nms[t];
        float aa = __fmul_rn(__fsub_rn(a.z, a.x), __fsub_rn(a.w, a.y));
        float mg = -1.f; int bi = 0;
        #pragma unroll 4
        for (int g = 0; g < NGT; ++g) {
            float4 gb = s_gt4[g];
            float yy1 = fmaxf(a.x, gb.x);
            float xx1 = fmaxf(a.y, gb.y);
            float yy2 = fminf(a.z, gb.z);
            float xx2 = fminf(a.w, gb.w);
            float inter = __fmul_rn(fmaxf(__fsub_rn(yy2, yy1), 0.f),
                                    fmaxf(__fsub_rn(xx2, xx1), 0.f));
            float gba = __fmul_rn(__fsub_rn(gb.z, gb.x), __fsub_rn(gb.w, gb.y));
            float denom = __fadd_rn(__fsub_rn(__fadd_rn(aa, gba), inter), 1e-7f);
            float iou = __fdiv_rn(inter, denom);
            if (iou > mg) { mg = iou; bi = g; }
        }
        s_merged[t] = mg; s_gtbest[t] = bi;
    }
    __syncthreads();

    if (t < TOPN) {
        float mg = s_merged[t];
        int r = 0;
        for (int j = 0; j < TOPN; ++j) {
            float mj = s_merged[j];
            if (mj > mg || (mj == mg && j < t)) ++r;
        }
        if (r < TPOS) {
            float4 a = s_nms[t];
            float* roi = out + ((size_t)b * 128 + r) * 4;
            roi[0] = a.x; roi[1] = a.y; roi[2] = a.z; roi[3] = a.w;
            out[(size_t)BATCH * 128 * 4 + (size_t)b * TPOS + r] = (float)s_gtbest[t];
        }
    }
    for (int j = t; j < 64 * 4; j += THREADS) {
        out[((size_t)b * 128 + TPOS) * 4 + j] = 0.f;
    }
}

extern "C" void kernel_launch(void* const* d_in, const int* in_sizes, int n_in,
                              void* d_out, int out_size) {
    const float* deltas  = (const float*)d_in[0];
    const float* labels  = (const float*)d_in[1];
    const float* anchors = (const float*)d_in[2];
    const float* gt      = (const float*)d_in[3];
    float* out = (float*)d_out;
    cudaFuncSetAttribute(roi_kernel, cudaFuncAttributeMaxDynamicSharedMemorySize,
                         DYN_BYTES);
    roi_kernel<<<BATCH, THREADS, DYN_BYTES>>>(deltas, labels, anchors, gt, out);
}